// round 16
// baseline (speedup 1.0000x reference)
#include <cuda_runtime.h>

#define BQ    4
#define NQ    8192
#define G     32
#define NC    (G * G * G)          // 32768 cells per batch
#define GRID_MIN (-3.0f)
#define CELL     (6.0f / G)        // 0.1875
#define INV_CELL (G / 6.0f)
#define FULLM 0xFFFFFFFFu

// ---- scratch (__device__ globals; no allocation) ----
__device__ int    g_cnt[BQ * NC];
__device__ int    g_start[BQ * (NC + 1)];
__device__ int    g_cur[BQ * NC];
__device__ float4 g_ref[BQ * NQ];    // cell-sorted refs (x,y,z,0)
__device__ float  g_nn[BQ * NQ];     // nn sq dist per query (original index)
__device__ float  g_part[128];

__device__ __forceinline__ int clampi(int v, int lo, int hi) {
    return v < lo ? lo : (v > hi ? hi : v);
}
__device__ __forceinline__ void cell_coords(float x, float y, float z,
                                            int& cx, int& cy, int& cz) {
    cx = clampi((int)floorf((x - GRID_MIN) * INV_CELL), 0, G - 1);
    cy = clampi((int)floorf((y - GRID_MIN) * INV_CELL), 0, G - 1);
    cz = clampi((int)floorf((z - GRID_MIN) * INV_CELL), 0, G - 1);
}

// 1) zero ref cell counts
__global__ void k_zero() {
    int i = blockIdx.x * blockDim.x + threadIdx.x;
    if (i < BQ * NC) g_cnt[i] = 0;
}

// 2) count refs per cell
__global__ void k_count(const float* __restrict__ pc1w) {
    int t = blockIdx.x * blockDim.x + threadIdx.x;
    if (t >= BQ * NQ) return;
    int b = t >> 13, i = t & (NQ - 1);
    float x = pc1w[b * 3 * NQ + i];
    float y = pc1w[b * 3 * NQ + NQ + i];
    float z = pc1w[b * 3 * NQ + 2 * NQ + i];
    int cx, cy, cz; cell_coords(x, y, z, cx, cy, cz);
    atomicAdd(&g_cnt[b * NC + (cz * G + cy) * G + cx], 1);
}

// 3) exclusive scan per batch: 4 blocks x 1024 threads, 32 cells/thread
__global__ __launch_bounds__(1024) void k_scan() {
    __shared__ int ssum[1024];
    int b = blockIdx.x;
    int* cnt   = g_cnt + b * NC;
    int* start = g_start + b * (NC + 1);
    int* cur   = g_cur + b * NC;
    int tid = threadIdx.x;
    int base = tid * 32;
    int sum = 0;
#pragma unroll
    for (int k = 0; k < 32; k++) sum += cnt[base + k];
    ssum[tid] = sum;
    __syncthreads();
    for (int off = 1; off < 1024; off <<= 1) {
        int v = (tid >= off) ? ssum[tid - off] : 0;
        __syncthreads();
        if (tid >= off) ssum[tid] += v;
        __syncthreads();
    }
    int run = ssum[tid] - sum;              // exclusive
#pragma unroll
    for (int k = 0; k < 32; k++) {
        int v = cnt[base + k];
        start[base + k] = run;
        cur[base + k] = run;
        run += v;
    }
    if (tid == 1023) start[NC] = run;
}

// 4) scatter refs into cell-sorted float4 array
__global__ void k_scatter(const float* __restrict__ pc1w) {
    int t = blockIdx.x * blockDim.x + threadIdx.x;
    if (t >= BQ * NQ) return;
    int b = t >> 13, i = t & (NQ - 1);
    float x = pc1w[b * 3 * NQ + i];
    float y = pc1w[b * 3 * NQ + NQ + i];
    float z = pc1w[b * 3 * NQ + 2 * NQ + i];
    int cx, cy, cz; cell_coords(x, y, z, cx, cy, cz);
    int pos = atomicAdd(&g_cur[b * NC + (cz * G + cy) * G + cx], 1);
    g_ref[b * NQ + pos] = make_float4(x, y, z, 0.0f);
}

// Warp-cooperative scan of the FULL cube radius r around (cx,cy,cz).
// Rows chunked 32/pass: shfl prefix over row counts, row table in smem,
// then all 32 lanes stream candidates with coalesced float4 loads.
// Returns warp-reduced min squared distance (all lanes).
__device__ float scan_cube(const int* __restrict__ start,
                           const float4* __restrict__ ref,
                           float x, float y, float z,
                           int cx, int cy, int cz, int r, int lane,
                           volatile int* sp, volatile int* sc, volatile int* ss) {
    int side = 2 * r + 1, nrows = side * side;
    int x0 = max(cx - r, 0), x1 = min(cx + r, G - 1);
    float best = 3.0e38f;
    for (int rb = 0; rb < nrows; rb += 32) {
        int w = rb + lane;
        int s0 = 0, cnt = 0;
        if (w < nrows) {
            int dz = w / side - r, dy = w % side - r;
            int zz = cz + dz, yy = cy + dy;
            if (zz >= 0 && zz < G && yy >= 0 && yy < G) {
                int rowbase = (zz * G + yy) * G;
                s0 = start[rowbase + x0];
                cnt = start[rowbase + x1 + 1] - s0;
            }
        }
        int incl = cnt;
#pragma unroll
        for (int o = 1; o < 32; o <<= 1) {
            int v = __shfl_up_sync(FULLM, incl, o);
            if (lane >= o) incl += v;
        }
        int total = __shfl_sync(FULLM, incl, 31);
        sp[lane] = incl - cnt;    // exclusive prefix
        sc[lane] = cnt;
        ss[lane] = s0;
        __syncwarp();
        int k = 0;                 // monotonic row pointer per lane
        for (int base2 = 0; base2 < total; base2 += 32) {
            int i = base2 + lane;
            if (i < total) {
                while (i >= sp[k] + sc[k]) k++;
                float4 rp = ref[ss[k] + (i - sp[k])];
                float ddx = rp.x - x, ddy = rp.y - y, ddz = rp.z - z;
                best = fminf(best, fmaf(ddx, ddx, fmaf(ddy, ddy, ddz * ddz)));
            }
        }
        __syncwarp();
    }
#pragma unroll
    for (int o = 16; o > 0; o >>= 1)
        best = fminf(best, __shfl_xor_sync(FULLM, best, o));
    return best;
}

// 5) exact 1-NN, one warp per query. Pass 1: cube r=1. Then JUMP directly to
// the radius the clamp-safe Chebyshev bound requires (one more pass), instead
// of incrementally walking rings. Empty neighborhoods double r.
__global__ __launch_bounds__(256) void k_nn(const float* __restrict__ pc2) {
    __shared__ int sp[8][32], sc[8][32], ss[8][32];
    int gt = blockIdx.x * blockDim.x + threadIdx.x;
    int warp = gt >> 5;                    // 0 .. BQ*NQ-1
    int lane = threadIdx.x & 31;
    int wl = threadIdx.x >> 5;
    int b = warp >> 13, qi = warp & (NQ - 1);

    float x = pc2[b * 3 * NQ + qi];
    float y = pc2[b * 3 * NQ + NQ + qi];
    float z = pc2[b * 3 * NQ + 2 * NQ + qi];
    int cx, cy, cz; cell_coords(x, y, z, cx, cy, cz);

    const int*    start = g_start + b * (NC + 1);
    const float4* ref   = g_ref + b * NQ;

    float best = 3.0e38f;
    int r = 1;
    while (true) {
        best = fminf(best, scan_cube(start, ref, x, y, z, cx, cy, cz, r, lane,
                                     sp[wl], sc[wl], ss[wl]));
        bool full = (cx - r <= 0) && (cx + r >= G - 1) &&
                    (cy - r <= 0) && (cy + r >= G - 1) &&
                    (cz - r <= 0) && (cz + r >= G - 1);
        if (best < 1.0e37f) {
            // smallest rn with (rn*CELL)^2 >= best  (clamp-safe simple bound)
            int rn = (int)ceilf(sqrtf(best) * INV_CELL);
            while ((float)rn * CELL * ((float)rn * CELL) < best) rn++;
            if (rn <= r || full) break;
            r = rn < G ? rn : G;
        } else {
            if (full) break;
            r = (2 * r < G) ? 2 * r : G;
        }
    }

    if (lane == 0) g_nn[b * NQ + qi] = best;   // >= 0 by construction
}

// 6) fixed-order reduction: 128 blocks x 256, one value per thread
__global__ __launch_bounds__(256) void k_red() {
    __shared__ float red[256];
    int tid = threadIdx.x;
    red[tid] = g_nn[blockIdx.x * 256 + tid];
    __syncthreads();
#pragma unroll
    for (int st = 128; st > 0; st >>= 1) {
        if (tid < st) red[tid] += red[tid + st];
        __syncthreads();
    }
    if (tid == 0) g_part[blockIdx.x] = red[0];
}

// 7) final: loss = 2 * mean_b(sum_n nn) = (2/BQ) * total
__global__ __launch_bounds__(128) void k_final(float* __restrict__ out) {
    __shared__ float red[128];
    int tid = threadIdx.x;
    red[tid] = g_part[tid];
    __syncthreads();
#pragma unroll
    for (int st = 64; st > 0; st >>= 1) {
        if (tid < st) red[tid] += red[tid + st];
        __syncthreads();
    }
    if (tid == 0) out[0] = red[0] * (2.0f / BQ);
}

extern "C" void kernel_launch(void* const* d_in, const int* in_sizes, int n_in,
                              void* d_out, int out_size) {
    const float* pc2  = (const float*)d_in[0];   // queries
    const float* pc1w = (const float*)d_in[1];   // refs
    float* out = (float*)d_out;

    k_zero<<<(BQ * NC + 255) / 256, 256>>>();
    k_count<<<(BQ * NQ + 255) / 256, 256>>>(pc1w);
    k_scan<<<BQ, 1024>>>();
    k_scatter<<<(BQ * NQ + 255) / 256, 256>>>(pc1w);
    k_nn<<<(BQ * NQ * 32) / 256, 256>>>(pc2);
    k_red<<<128, 256>>>();
    k_final<<<1, 128>>>(out);
}

// round 17
// speedup vs baseline: 2.6766x; 2.6766x over previous
#include <cuda_runtime.h>

#define BQ    4
#define NQ    8192
#define G     32
#define NC    (G * G * G)          // 32768 cells per batch
#define GRID_MIN (-3.0f)
#define CELL     (6.0f / G)        // 0.1875
#define INV_CELL (G / 6.0f)
#define FULLM 0xFFFFFFFFu

// ---- scratch (__device__ globals; no allocation) ----
__device__ int    g_cnt[BQ * NC];
__device__ int    g_start[BQ * (NC + 1)];
__device__ int    g_cur[BQ * NC];
__device__ float4 g_ref[BQ * NQ];    // cell-sorted refs (x,y,z,0)
__device__ float  g_part1[(BQ * NQ) / 8];  // one partial per k_nn block (4096)

__device__ __forceinline__ int clampi(int v, int lo, int hi) {
    return v < lo ? lo : (v > hi ? hi : v);
}
__device__ __forceinline__ void cell_coords(float x, float y, float z,
                                            int& cx, int& cy, int& cz) {
    cx = clampi((int)floorf((x - GRID_MIN) * INV_CELL), 0, G - 1);
    cy = clampi((int)floorf((y - GRID_MIN) * INV_CELL), 0, G - 1);
    cz = clampi((int)floorf((z - GRID_MIN) * INV_CELL), 0, G - 1);
}

// 1) zero ref cell counts
__global__ void k_zero() {
    int i = blockIdx.x * blockDim.x + threadIdx.x;
    if (i < BQ * NC) g_cnt[i] = 0;
}

// 2) count refs per cell
__global__ void k_count(const float* __restrict__ pc1w) {
    int t = blockIdx.x * blockDim.x + threadIdx.x;
    if (t >= BQ * NQ) return;
    int b = t >> 13, i = t & (NQ - 1);
    float x = pc1w[b * 3 * NQ + i];
    float y = pc1w[b * 3 * NQ + NQ + i];
    float z = pc1w[b * 3 * NQ + 2 * NQ + i];
    int cx, cy, cz; cell_coords(x, y, z, cx, cy, cz);
    atomicAdd(&g_cnt[b * NC + (cz * G + cy) * G + cx], 1);
}

// 3) exclusive scan per batch: 4 blocks x 1024 threads, 32 cells/thread
__global__ __launch_bounds__(1024) void k_scan() {
    __shared__ int ssum[1024];
    int b = blockIdx.x;
    int* cnt   = g_cnt + b * NC;
    int* start = g_start + b * (NC + 1);
    int* cur   = g_cur + b * NC;
    int tid = threadIdx.x;
    int base = tid * 32;
    int sum = 0;
#pragma unroll
    for (int k = 0; k < 32; k++) sum += cnt[base + k];
    ssum[tid] = sum;
    __syncthreads();
    for (int off = 1; off < 1024; off <<= 1) {
        int v = (tid >= off) ? ssum[tid - off] : 0;
        __syncthreads();
        if (tid >= off) ssum[tid] += v;
        __syncthreads();
    }
    int run = ssum[tid] - sum;              // exclusive
#pragma unroll
    for (int k = 0; k < 32; k++) {
        int v = cnt[base + k];
        start[base + k] = run;
        cur[base + k] = run;
        run += v;
    }
    if (tid == 1023) start[NC] = run;
}

// 4) scatter refs into cell-sorted float4 array
__global__ void k_scatter(const float* __restrict__ pc1w) {
    int t = blockIdx.x * blockDim.x + threadIdx.x;
    if (t >= BQ * NQ) return;
    int b = t >> 13, i = t & (NQ - 1);
    float x = pc1w[b * 3 * NQ + i];
    float y = pc1w[b * 3 * NQ + NQ + i];
    float z = pc1w[b * 3 * NQ + 2 * NQ + i];
    int cx, cy, cz; cell_coords(x, y, z, cx, cy, cz);
    int pos = atomicAdd(&g_cur[b * NC + (cz * G + cy) * G + cx], 1);
    g_ref[b * NQ + pos] = make_float4(x, y, z, 0.0f);
}

// Warp-cooperative scan of an arbitrary cell box [x0..x1]x[y0..y1]x[z0..z1].
// Rows chunked 32/pass; shfl prefix over row counts; non-volatile smem tables;
// candidates streamed coalesced, row found by 5-step unrolled binary search.
__device__ float scan_box(const int* __restrict__ start,
                          const float4* __restrict__ ref,
                          float x, float y, float z,
                          int x0, int x1, int y0, int y1, int z0, int z1,
                          int lane, int* spfx_s, int* sst_s) {
    int ny = y1 - y0 + 1;
    int nrows = ny * (z1 - z0 + 1);
    float best = 3.0e38f;
    for (int rb = 0; rb < nrows; rb += 32) {
        int w = rb + lane;
        int s0 = 0, cnt = 0;
        if (w < nrows) {
            int q = w / ny;
            int zz = z0 + q, yy = y0 + (w - q * ny);
            int rowbase = (zz * G + yy) * G;
            s0 = start[rowbase + x0];
            cnt = start[rowbase + x1 + 1] - s0;
        }
        int incl = cnt;
#pragma unroll
        for (int o = 1; o < 32; o <<= 1) {
            int v = __shfl_up_sync(FULLM, incl, o);
            if (lane >= o) incl += v;
        }
        int total = __shfl_sync(FULLM, incl, 31);
        int excl = incl - cnt;
        __syncwarp();
        spfx_s[lane] = excl;
        sst_s[lane] = s0 - excl;     // addr = sst_s[k] + i
        __syncwarp();
        for (int b2 = 0; b2 < total; b2 += 32) {
            int i = b2 + lane;
            if (i < total) {
                int k = 0;           // largest k with spfx_s[k] <= i
#pragma unroll
                for (int step = 16; step >= 1; step >>= 1) {
                    int c = k + step;
                    if (c < 32 && spfx_s[c] <= i) k = c;
                }
                float4 rp = ref[sst_s[k] + i];
                float ddx = rp.x - x, ddy = rp.y - y, ddz = rp.z - z;
                best = fminf(best, fmaf(ddx, ddx, fmaf(ddy, ddy, ddz * ddz)));
            }
        }
        __syncwarp();
    }
#pragma unroll
    for (int o = 16; o > 0; o >>= 1)
        best = fminf(best, __shfl_xor_sync(FULLM, best, o));
    return best;
}

// 5) exact 1-NN, one warp per query.
// Pass A: r=1 cube, register-table lane-per-candidate (proven R12 path).
// Tight clamp-safe face bound; rare pass B: single ball-box scan (exact).
__global__ __launch_bounds__(256) void k_nn(const float* __restrict__ pc2) {
    __shared__ int spfx_s[8][32], sst_s[8][32];
    __shared__ float wres[8];
    int gt = blockIdx.x * blockDim.x + threadIdx.x;
    int warp = gt >> 5;                    // 0 .. BQ*NQ-1
    int lane = threadIdx.x & 31;
    int wl = threadIdx.x >> 5;
    int b = warp >> 13, qi = warp & (NQ - 1);

    float x = pc2[b * 3 * NQ + qi];
    float y = pc2[b * 3 * NQ + NQ + qi];
    float z = pc2[b * 3 * NQ + 2 * NQ + qi];
    int cx, cy, cz; cell_coords(x, y, z, cx, cy, cz);

    const int*    start = g_start + b * (NC + 1);
    const float4* ref   = g_ref + b * NQ;

    // ---- pass A: 9 row-ranges of the r<=1 cube, register tables ----
    int my_s0 = 0, my_cnt = 0;
    if (lane < 9) {
        int dz = lane / 3 - 1, dy = lane % 3 - 1;
        int zz = cz + dz, yy = cy + dy;
        if (zz >= 0 && zz < G && yy >= 0 && yy < G) {
            int rowbase = (zz * G + yy) * G;
            int x0 = max(cx - 1, 0), x1 = min(cx + 1, G - 1);
            my_s0 = start[rowbase + x0];
            my_cnt = start[rowbase + x1 + 1] - my_s0;
        }
    }
    int incl = my_cnt;
#pragma unroll
    for (int o = 1; o < 16; o <<= 1) {
        int v = __shfl_up_sync(FULLM, incl, o);
        if (lane >= o) incl += v;
    }
    int my_p = incl - my_cnt;
    int total = __shfl_sync(FULLM, incl, 8);

    int pk[9], ck[9], sk[9];
#pragma unroll
    for (int k = 0; k < 9; k++) {
        pk[k] = __shfl_sync(FULLM, my_p, k);
        ck[k] = __shfl_sync(FULLM, my_cnt, k);
        sk[k] = __shfl_sync(FULLM, my_s0, k);
    }

    float best = 3.0e38f;
    for (int base = 0; base < total; base += 32) {
        int i = base + lane;
        if (i < total) {
            int addr = 0;
#pragma unroll
            for (int k = 0; k < 9; k++)
                if (i >= pk[k] && i < pk[k] + ck[k]) addr = sk[k] + (i - pk[k]);
            float4 rp = ref[addr];
            float dx = rp.x - x, dy = rp.y - y, dz = rp.z - z;
            best = fminf(best, fmaf(dx, dx, fmaf(dy, dy, dz * dz)));
        }
    }
#pragma unroll
    for (int o = 16; o > 0; o >>= 1)
        best = fminf(best, __shfl_xor_sync(FULLM, best, o));

    // ---- tight clamp-safe bound: distance to finite faces of scanned box ----
    // Grid-edge faces extend to infinity (clamped refs live in boundary cells).
    float dxl = (cx - 1 > 0)     ? x - (GRID_MIN + (cx - 1) * CELL) : 3.0e38f;
    float dxh = (cx + 1 < G - 1) ? (GRID_MIN + (cx + 2) * CELL) - x : 3.0e38f;
    float dyl = (cy - 1 > 0)     ? y - (GRID_MIN + (cy - 1) * CELL) : 3.0e38f;
    float dyh = (cy + 1 < G - 1) ? (GRID_MIN + (cy + 2) * CELL) - y : 3.0e38f;
    float dzl = (cz - 1 > 0)     ? z - (GRID_MIN + (cz - 1) * CELL) : 3.0e38f;
    float dzh = (cz + 1 < G - 1) ? (GRID_MIN + (cz + 2) * CELL) - z : 3.0e38f;
    float dmin = fminf(fminf(fminf(dxl, dxh), fminf(dyl, dyh)), fminf(dzl, dzh));

    if (best > dmin * dmin) {
        // rare: empty neighborhood -> expand cubes until any point found
        int r = 2;
        while (best >= 3.0e38f) {
            int X0 = max(cx - r, 0), X1 = min(cx + r, G - 1);
            int Y0 = max(cy - r, 0), Y1 = min(cy + r, G - 1);
            int Z0 = max(cz - r, 0), Z1 = min(cz + r, G - 1);
            best = fminf(best, scan_box(start, ref, x, y, z,
                                        X0, X1, Y0, Y1, Z0, Z1,
                                        lane, spfx_s[wl], sst_s[wl]));
            if (X0 == 0 && Y0 == 0 && Z0 == 0 &&
                X1 == G - 1 && Y1 == G - 1 && Z1 == G - 1) break;
            r <<= 1;
        }
        // single exact ball-box pass (box of cells intersecting ball(q, s))
        float s = sqrtf(best) * (1.0f + 1.0e-4f) + 1.0e-6f;
        int X0 = clampi((int)floorf((x - s - GRID_MIN) * INV_CELL), 0, G - 1);
        int X1 = clampi((int)floorf((x + s - GRID_MIN) * INV_CELL), 0, G - 1);
        int Y0 = clampi((int)floorf((y - s - GRID_MIN) * INV_CELL), 0, G - 1);
        int Y1 = clampi((int)floorf((y + s - GRID_MIN) * INV_CELL), 0, G - 1);
        int Z0 = clampi((int)floorf((z - s - GRID_MIN) * INV_CELL), 0, G - 1);
        int Z1 = clampi((int)floorf((z + s - GRID_MIN) * INV_CELL), 0, G - 1);
        best = fminf(best, scan_box(start, ref, x, y, z,
                                    X0, X1, Y0, Y1, Z0, Z1,
                                    lane, spfx_s[wl], sst_s[wl]));
    }

    // block partial: 8 warp results, fixed order -> g_part1[block]
    if (lane == 0) wres[wl] = best;
    __syncthreads();
    if (threadIdx.x == 0) {
        float a = 0.0f;
#pragma unroll
        for (int k = 0; k < 8; k++) a += wres[k];
        g_part1[blockIdx.x] = a;
    }
}

// 6) final: 1 block, deterministic fixed-order sum of 4096 partials.
// loss = 2 * mean_b(sum_n nn) = (2/BQ) * total
__global__ __launch_bounds__(1024) void k_final(float* __restrict__ out) {
    __shared__ float red[1024];
    int tid = threadIdx.x;
    float a = g_part1[tid];
    a += g_part1[tid + 1024];
    a += g_part1[tid + 2048];
    a += g_part1[tid + 3072];
    red[tid] = a;
    __syncthreads();
#pragma unroll
    for (int st = 512; st > 0; st >>= 1) {
        if (tid < st) red[tid] += red[tid + st];
        __syncthreads();
    }
    if (tid == 0) out[0] = red[0] * (2.0f / BQ);
}

extern "C" void kernel_launch(void* const* d_in, const int* in_sizes, int n_in,
                              void* d_out, int out_size) {
    const float* pc2  = (const float*)d_in[0];   // queries
    const float* pc1w = (const float*)d_in[1];   // refs
    float* out = (float*)d_out;

    k_zero<<<(BQ * NC + 255) / 256, 256>>>();
    k_count<<<(BQ * NQ + 255) / 256, 256>>>(pc1w);
    k_scan<<<BQ, 1024>>>();
    k_scatter<<<(BQ * NQ + 255) / 256, 256>>>(pc1w);
    k_nn<<<(BQ * NQ * 32) / 256, 256>>>(pc2);
    k_final<<<1, 1024>>>(out);
}